// round 7
// baseline (speedup 1.0000x reference)
#include <cuda_runtime.h>
#include <cstdint>

// ---------------------------------------------------------------------------
// Constants (derived at compile time from reference _compute_offsets()):
//   Level l: scale = 16*2^l - 1, resolution = 16*2^l, verts/axis r1 = 16*2^l+1
//   Dense levels: 0 (r1=17, off 0), 1 (r1=33, off 4920), 2 (r1=65, off 40864)
//   Hashed levels 3..15: 2^19 entries each -> mask; off = 315496+(l-3)*524288
//   TOTAL = 7131240
// ---------------------------------------------------------------------------

#define TOTAL_PARAMS 7131240
#define DENSE_TOTAL  315496
#define HASH_MASK    0x7FFFFu
#define PRIME_Y      2654435761u
#define PRIME_Z      805459861u

// Accumulator (85.6 MB total -> L2-resident on GB300):
__device__ __align__(16) float2   g_sum2[TOTAL_PARAMS];   // 57 MB
__device__ __align__(16) unsigned g_cnt[TOTAL_PARAMS];    // 28.5 MB
// Finalized table + dense x-pair table:
__device__ __align__(16) float2 g_table[TOTAL_PARAMS];    // 57 MB
__device__ __align__(16) float4 g_dense4[DENSE_TOTAL];    //  5 MB

// ---------------------------------------------------------------------------
// Scatter: 4 points/thread, vectorized streaming reads, 8 independent
// fire-and-forget REDs (RED.64 sum + RED.32 count per point).
// ---------------------------------------------------------------------------
__global__ void __launch_bounds__(256) scatter_kernel(
    const float2* __restrict__ emb, const int* __restrict__ sidx, int n) {
    int t = blockIdx.x * blockDim.x + threadIdx.x;
    int i = t * 4;
    if (i + 3 < n) {
        int4   idx = *reinterpret_cast<const int4*>(sidx + i);
        float4 e01 = *reinterpret_cast<const float4*>(emb + i);
        float4 e23 = *reinterpret_cast<const float4*>(emb + i + 2);
        atomicAdd(&g_sum2[idx.x], make_float2(e01.x, e01.y));
        atomicAdd(&g_sum2[idx.y], make_float2(e01.z, e01.w));
        atomicAdd(&g_sum2[idx.z], make_float2(e23.x, e23.y));
        atomicAdd(&g_sum2[idx.w], make_float2(e23.z, e23.w));
        atomicAdd(&g_cnt[idx.x], 1u);
        atomicAdd(&g_cnt[idx.y], 1u);
        atomicAdd(&g_cnt[idx.z], 1u);
        atomicAdd(&g_cnt[idx.w], 1u);
    } else {
        for (; i < n; ++i) {
            int id = sidx[i];
            atomicAdd(&g_sum2[id], emb[i]);
            atomicAdd(&g_cnt[id], 1u);
        }
    }
}

// ---------------------------------------------------------------------------
// Finalize (fused with dense pack):
//   table[i] = cnt>0 ? sum/cnt : fs[i]
//   for i < DENSE_TOTAL also emit g_dense4[i] = {v(i), v(i+1)} so dense-level
//   x-neighbor corners load as one aligned float4 in encode.
// ---------------------------------------------------------------------------
__device__ __forceinline__ float2 vert_value(const float2* __restrict__ fs, int i) {
    unsigned c = g_cnt[i];
    if (c > 0u) {
        float2 s = g_sum2[i];
        float inv = 1.0f / (float)c;
        return make_float2(s.x * inv, s.y * inv);
    }
    return fs[i];
}

__global__ void __launch_bounds__(256) finalize_kernel(
    const float2* __restrict__ fs, int n) {
    int i = blockIdx.x * blockDim.x + threadIdx.x;
    if (i >= n) return;
    float2 v = vert_value(fs, i);
    g_table[i] = v;
    if (i < DENSE_TOTAL) {
        float2 v1 = vert_value(fs, i + 1);   // in-bounds: DENSE_TOTAL < TOTAL
        g_dense4[i] = make_float4(v.x, v.y, v1.x, v1.y);
    }
}

// ---------------------------------------------------------------------------
// Re-zero the accumulator for the next replay. Runs on a side stream
// concurrent with encode (encode never touches g_sum2/g_cnt).
// ---------------------------------------------------------------------------
__global__ void __launch_bounds__(256) zero_acc_kernel() {
    float4* s = reinterpret_cast<float4*>(g_sum2);
    uint4*  c = reinterpret_cast<uint4*>(g_cnt);
    const size_t ns = (size_t)TOTAL_PARAMS / 2;   // float4 count (TOTAL even)
    const size_t nc = (size_t)TOTAL_PARAMS / 4;
    const size_t stride = (size_t)gridDim.x * blockDim.x;
    size_t t = (size_t)blockIdx.x * blockDim.x + threadIdx.x;
    for (size_t i = t; i < ns; i += stride) s[i] = make_float4(0.f, 0.f, 0.f, 0.f);
    for (size_t i = t; i < nc; i += stride) c[i] = make_uint4(0u, 0u, 0u, 0u);
}

// ---------------------------------------------------------------------------
// Encode: thread-per-point, 16 levels fully unrolled. Dense levels: 4 aligned
// float4 pair-gathers. Hash levels: 8 float2 gathers.
// ---------------------------------------------------------------------------
__global__ void __launch_bounds__(256) encode_kernel(
    const float* __restrict__ inp,
    const int*   __restrict__ bound_ptr,
    float*       __restrict__ out,
    int B) {
    int b = blockIdx.x * blockDim.x + threadIdx.x;
    if (b >= B) return;

    float bound = 1.0f;
    if (bound_ptr) {
        int raw = bound_ptr[0];
        bound = (raw > 0 && raw < 1000000) ? (float)raw : __int_as_float(raw);
    }
    const float half_inv = 0.5f / bound;

    float x0 = (inp[3 * b + 0] + bound) * half_inv;
    float x1 = (inp[3 * b + 1] + bound) * half_inv;
    float x2 = (inp[3 * b + 2] + bound) * half_inv;

    float r[32];

#pragma unroll
    for (int l = 0; l < 16; ++l) {
        const float scale = (float)((16 << l) - 1);
        float p0 = x0 * scale + 0.5f;      // align_corners=False offset
        float p1 = x1 * scale + 0.5f;
        float p2 = x2 * scale + 0.5f;
        float g0 = floorf(p0), g1 = floorf(p1), g2 = floorf(p2);
        float f0 = p0 - g0, f1 = p1 - g1, f2 = p2 - g2;
        int   i0 = (int)g0, i1 = (int)g1, i2 = (int)g2;

        const float wx0 = 1.0f - f0;
        const float wy0 = 1.0f - f1, wy1 = f1;
        const float wz0 = 1.0f - f2, wz1 = f2;
        float ax, ay;

        if (l < 3) {
            // Dense level: x-pair packed float4 gathers (4 loads).
            const int r1  = (l == 0) ? 17 : (l == 1) ? 33 : 65;
            const int off = (l == 0) ? 0  : (l == 1) ? 4920 : 40864;
            const int r1s = r1 * r1;
            int base = off + i0 + i1 * r1 + i2 * r1s;
            float4 d00 = __ldg(&g_dense4[base]);
            float4 d10 = __ldg(&g_dense4[base + r1]);
            float4 d01 = __ldg(&g_dense4[base + r1s]);
            float4 d11 = __ldg(&g_dense4[base + r1 + r1s]);
            float w00 = wy0 * wz0, w10 = wy1 * wz0;
            float w01 = wy0 * wz1, w11 = wy1 * wz1;
            ax = w00 * fmaf(wx0, d00.x, f0 * d00.z)
               + w10 * fmaf(wx0, d10.x, f0 * d10.z)
               + w01 * fmaf(wx0, d01.x, f0 * d01.z)
               + w11 * fmaf(wx0, d11.x, f0 * d11.z);
            ay = w00 * fmaf(wx0, d00.y, f0 * d00.w)
               + w10 * fmaf(wx0, d10.y, f0 * d10.w)
               + w01 * fmaf(wx0, d01.y, f0 * d01.w)
               + w11 * fmaf(wx0, d11.y, f0 * d11.w);
        } else {
            // Hashed level: xor of per-dim prime products, mask 2^19-1.
            const int off = 315496 + (l - 3) * 524288;
            unsigned hx0 = (unsigned)i0;
            unsigned hx1 = hx0 + 1u;
            unsigned hy0 = (unsigned)i1 * PRIME_Y;
            unsigned hy1 = hy0 + PRIME_Y;
            unsigned hz0 = (unsigned)i2 * PRIME_Z;
            unsigned hz1 = hz0 + PRIME_Z;
            unsigned idx[8];
#pragma unroll
            for (int c = 0; c < 8; ++c) {
                unsigned h = ((c & 1) ? hx1 : hx0) ^
                             (((c >> 1) & 1) ? hy1 : hy0) ^
                             (((c >> 2) & 1) ? hz1 : hz0);
                idx[c] = h & HASH_MASK;
            }
            float2 v[8];
#pragma unroll
            for (int c = 0; c < 8; ++c)
                v[c] = __ldg(&g_table[off + (int)idx[c]]);
            ax = 0.0f; ay = 0.0f;
#pragma unroll
            for (int c = 0; c < 8; ++c) {
                float w = ((c & 1) ? f0 : wx0) *
                          (((c >> 1) & 1) ? wy1 : wy0) *
                          (((c >> 2) & 1) ? wz1 : wz0);
                ax = fmaf(w, v[c].x, ax);
                ay = fmaf(w, v[c].y, ay);
            }
        }
        r[2 * l]     = ax;
        r[2 * l + 1] = ay;
    }

    float4* o = (float4*)(out + (size_t)b * 32);
#pragma unroll
    for (int i = 0; i < 8; ++i)
        o[i] = make_float4(r[4 * i], r[4 * i + 1], r[4 * i + 2], r[4 * i + 3]);
}

// ---------------------------------------------------------------------------
// Launcher. Graph-capturable: kernel launches + event fork/join only.
//   scatter -> finalize(+pack) -> encode            (main stream)
//                            \-> zero_acc            (side stream, joined)
// zero_acc prepares g_sum2/g_cnt for the NEXT replay; first call relies on
// static zero-init of __device__ globals. encode never reads the accumulator,
// so the overlap is race-free; the join makes replay N+1's scatter observe
// the zeroed accumulator.
// ---------------------------------------------------------------------------
extern "C" void kernel_launch(void* const* d_in, const int* in_sizes, int n_in,
                              void* d_out, int out_size) {
    const float*  inputs = (const float*) d_in[0];
    const float2* emb    = (const float2*)d_in[1];
    const float2* fs     = (const float2*)d_in[2];
    const int*    sidx   = (const int*)   d_in[3];
    const int*    bound  = (n_in >= 5) ? (const int*)d_in[4] : nullptr;

    int npts = in_sizes[3];          // 2,000,000
    int B    = in_sizes[0] / 3;      // 262,144

    int sc_threads = (npts + 3) / 4;
    scatter_kernel<<<(sc_threads + 255) / 256, 256>>>(emb, sidx, npts);
    finalize_kernel<<<(TOTAL_PARAMS + 255) / 256, 256>>>(fs, TOTAL_PARAMS);

    // Fork: zero_acc depends only on finalize (last reader of the accumulator).
    cudaStream_t side;
    cudaEvent_t ev_fork, ev_join;
    cudaStreamCreateWithFlags(&side, cudaStreamNonBlocking);
    cudaEventCreateWithFlags(&ev_fork, cudaEventDisableTiming);
    cudaEventCreateWithFlags(&ev_join, cudaEventDisableTiming);
    cudaEventRecord(ev_fork, 0);
    cudaStreamWaitEvent(side, ev_fork, 0);
    zero_acc_kernel<<<2048, 256, 0, side>>>();
    cudaEventRecord(ev_join, side);

    encode_kernel<<<(B + 255) / 256, 256>>>(inputs, bound, (float*)d_out, B);

    // Join: next replay's scatter must see the zeroed accumulator.
    cudaStreamWaitEvent(0, ev_join, 0);
}

// round 9
// speedup vs baseline: 1.0934x; 1.0934x over previous
#include <cuda_runtime.h>
#include <cstdint>

// ---------------------------------------------------------------------------
// Constants (derived at compile time from reference _compute_offsets()):
//   Level l: scale = 16*2^l - 1, resolution = 16*2^l, verts/axis r1 = 16*2^l+1
//   Dense levels: 0 (r1=17, off 0), 1 (r1=33, off 4920), 2 (r1=65, off 40864)
//   Hashed levels 3..15: 2^19 entries each -> mask; off = 315496+(l-3)*524288
//   TOTAL = 7131240 (even)
// ---------------------------------------------------------------------------

#define TOTAL_PARAMS 7131240
#define DENSE_TOTAL  315496
#define HASH_MASK    0x7FFFFu
#define PRIME_Y      2654435761u
#define PRIME_Z      805459861u

// Accumulator (85.6 MB total). Zero-initialized at module load; re-zeroed by
// finalize_kernel itself each call (element-wise, race-free).
__device__ __align__(16) float2   g_sum2[TOTAL_PARAMS];   // 57 MB
__device__ __align__(16) unsigned g_cnt[TOTAL_PARAMS];    // 28.5 MB
// Finalized table + dense x-pair table:
__device__ __align__(16) float2 g_table[TOTAL_PARAMS];    // 57 MB
__device__ __align__(16) float4 g_dense4[DENSE_TOTAL];    //  5 MB

// ---------------------------------------------------------------------------
// Scatter: 1 point/thread (R3-proven). RED.64 sum + RED.32 count,
// fire-and-forget; accumulator lines are L2-resident (just reset last call).
// ---------------------------------------------------------------------------
__global__ void __launch_bounds__(256) scatter_kernel(
    const float2* __restrict__ emb, const int* __restrict__ sidx, int n) {
    int i = blockIdx.x * blockDim.x + threadIdx.x;
    if (i >= n) return;
    int idx = sidx[i];
    float2 e = emb[i];
    atomicAdd(&g_sum2[idx], e);
    atomicAdd(&g_cnt[idx], 1u);
}

// ---------------------------------------------------------------------------
// Finalize (+ fused accumulator reset):
//   table[i] = cnt>0 ? sum/cnt : fs[i];  then sum[i]=0, cnt[i]=0.
// Processes 2 vertices/thread so all accumulator traffic is 16B/8B vectors.
// The zero-writes hit lines we just read (L2-dirty), and their writeback
// drains during the L1-bound encode kernel — the standalone zero kernel is
// deleted. Element-wise => race-free. First call: globals are zero-init.
// ---------------------------------------------------------------------------
__global__ void __launch_bounds__(256) finalize_kernel(
    const float4* __restrict__ fs4, int npairs) {
    int p = blockIdx.x * blockDim.x + threadIdx.x;
    if (p >= npairs) return;

    float4 s  = reinterpret_cast<const float4*>(g_sum2)[p]; // sums i, i+1
    uint2  c  = reinterpret_cast<const uint2*>(g_cnt)[p];   // counts i, i+1
    float4 fv = fs4[p];                                     // fs i, i+1

    float4 t;
    if (c.x > 0u) {
        float inv = 1.0f / (float)c.x;
        t.x = s.x * inv; t.y = s.y * inv;
    } else {
        t.x = fv.x; t.y = fv.y;
    }
    if (c.y > 0u) {
        float inv = 1.0f / (float)c.y;
        t.z = s.z * inv; t.w = s.w * inv;
    } else {
        t.z = fv.z; t.w = fv.w;
    }
    reinterpret_cast<float4*>(g_table)[p] = t;

    // Reset accumulator for the next replay.
    reinterpret_cast<float4*>(g_sum2)[p] = make_float4(0.f, 0.f, 0.f, 0.f);
    reinterpret_cast<uint2*>(g_cnt)[p]   = make_uint2(0u, 0u);
}

// ---------------------------------------------------------------------------
// Dense pair pack: g_dense4[i] = {table[i], table[i+1]} so dense-level
// x-neighbor corners load as one aligned float4. Reads are L2-hot (table was
// just written). Separate kernel to avoid racing finalize's acc reset.
// ---------------------------------------------------------------------------
__global__ void __launch_bounds__(256) dense_pack_kernel() {
    int i = blockIdx.x * blockDim.x + threadIdx.x;
    if (i >= DENSE_TOTAL) return;
    float2 a = g_table[i];
    float2 b = g_table[i + 1];      // in-bounds: DENSE_TOTAL < TOTAL_PARAMS
    g_dense4[i] = make_float4(a.x, a.y, b.x, b.y);
}

// ---------------------------------------------------------------------------
// Encode: thread-per-point, 16 levels fully unrolled. Dense levels: 4 aligned
// float4 pair-gathers. Hash levels: 8 float2 gathers. (R7-measured 97.2us.)
// ---------------------------------------------------------------------------
__global__ void __launch_bounds__(256) encode_kernel(
    const float* __restrict__ inp,
    const int*   __restrict__ bound_ptr,
    float*       __restrict__ out,
    int B) {
    int b = blockIdx.x * blockDim.x + threadIdx.x;
    if (b >= B) return;

    float bound = 1.0f;
    if (bound_ptr) {
        int raw = bound_ptr[0];
        bound = (raw > 0 && raw < 1000000) ? (float)raw : __int_as_float(raw);
    }
    const float half_inv = 0.5f / bound;

    float x0 = (inp[3 * b + 0] + bound) * half_inv;
    float x1 = (inp[3 * b + 1] + bound) * half_inv;
    float x2 = (inp[3 * b + 2] + bound) * half_inv;

    float r[32];

#pragma unroll
    for (int l = 0; l < 16; ++l) {
        const float scale = (float)((16 << l) - 1);
        float p0 = x0 * scale + 0.5f;      // align_corners=False offset
        float p1 = x1 * scale + 0.5f;
        float p2 = x2 * scale + 0.5f;
        float g0 = floorf(p0), g1 = floorf(p1), g2 = floorf(p2);
        float f0 = p0 - g0, f1 = p1 - g1, f2 = p2 - g2;
        int   i0 = (int)g0, i1 = (int)g1, i2 = (int)g2;

        const float wx0 = 1.0f - f0;
        const float wy0 = 1.0f - f1, wy1 = f1;
        const float wz0 = 1.0f - f2, wz1 = f2;
        float ax, ay;

        if (l < 3) {
            // Dense level: x-pair packed float4 gathers (4 loads).
            const int r1  = (l == 0) ? 17 : (l == 1) ? 33 : 65;
            const int off = (l == 0) ? 0  : (l == 1) ? 4920 : 40864;
            const int r1s = r1 * r1;
            int base = off + i0 + i1 * r1 + i2 * r1s;
            float4 d00 = __ldg(&g_dense4[base]);
            float4 d10 = __ldg(&g_dense4[base + r1]);
            float4 d01 = __ldg(&g_dense4[base + r1s]);
            float4 d11 = __ldg(&g_dense4[base + r1 + r1s]);
            float w00 = wy0 * wz0, w10 = wy1 * wz0;
            float w01 = wy0 * wz1, w11 = wy1 * wz1;
            ax = w00 * fmaf(wx0, d00.x, f0 * d00.z)
               + w10 * fmaf(wx0, d10.x, f0 * d10.z)
               + w01 * fmaf(wx0, d01.x, f0 * d01.z)
               + w11 * fmaf(wx0, d11.x, f0 * d11.z);
            ay = w00 * fmaf(wx0, d00.y, f0 * d00.w)
               + w10 * fmaf(wx0, d10.y, f0 * d10.w)
               + w01 * fmaf(wx0, d01.y, f0 * d01.w)
               + w11 * fmaf(wx0, d11.y, f0 * d11.w);
        } else {
            // Hashed level: xor of per-dim prime products, mask 2^19-1.
            const int off = 315496 + (l - 3) * 524288;
            unsigned hx0 = (unsigned)i0;
            unsigned hx1 = hx0 + 1u;
            unsigned hy0 = (unsigned)i1 * PRIME_Y;
            unsigned hy1 = hy0 + PRIME_Y;
            unsigned hz0 = (unsigned)i2 * PRIME_Z;
            unsigned hz1 = hz0 + PRIME_Z;
            unsigned idx[8];
#pragma unroll
            for (int c = 0; c < 8; ++c) {
                unsigned h = ((c & 1) ? hx1 : hx0) ^
                             (((c >> 1) & 1) ? hy1 : hy0) ^
                             (((c >> 2) & 1) ? hz1 : hz0);
                idx[c] = h & HASH_MASK;
            }
            float2 v[8];
#pragma unroll
            for (int c = 0; c < 8; ++c)
                v[c] = __ldg(&g_table[off + (int)idx[c]]);
            ax = 0.0f; ay = 0.0f;
#pragma unroll
            for (int c = 0; c < 8; ++c) {
                float w = ((c & 1) ? f0 : wx0) *
                          (((c >> 1) & 1) ? wy1 : wy0) *
                          (((c >> 2) & 1) ? wz1 : wz0);
                ax = fmaf(w, v[c].x, ax);
                ay = fmaf(w, v[c].y, ay);
            }
        }
        r[2 * l]     = ax;
        r[2 * l + 1] = ay;
    }

    float4* o = (float4*)(out + (size_t)b * 32);
#pragma unroll
    for (int i = 0; i < 8; ++i)
        o[i] = make_float4(r[4 * i], r[4 * i + 1], r[4 * i + 2], r[4 * i + 3]);
}

// ---------------------------------------------------------------------------
// Launcher: strictly serial, single stream, graph-capturable.
//   scatter -> finalize(+acc reset) -> dense_pack -> encode
// No side streams: concurrent bulk writes were evicting encode's L2-resident
// table (R6/R7 regression). The accumulator reset rides inside finalize.
// ---------------------------------------------------------------------------
extern "C" void kernel_launch(void* const* d_in, const int* in_sizes, int n_in,
                              void* d_out, int out_size) {
    const float*  inputs = (const float*) d_in[0];
    const float2* emb    = (const float2*)d_in[1];
    const float4* fs4    = (const float4*)d_in[2];
    const int*    sidx   = (const int*)   d_in[3];
    const int*    bound  = (n_in >= 5) ? (const int*)d_in[4] : nullptr;

    int npts = in_sizes[3];          // 2,000,000
    int B    = in_sizes[0] / 3;      // 262,144

    scatter_kernel<<<(npts + 255) / 256, 256>>>(emb, sidx, npts);

    int npairs = TOTAL_PARAMS / 2;   // 3,565,620
    finalize_kernel<<<(npairs + 255) / 256, 256>>>(fs4, npairs);

    dense_pack_kernel<<<(DENSE_TOTAL + 255) / 256, 256>>>();

    encode_kernel<<<(B + 255) / 256, 256>>>(inputs, bound, (float*)d_out, B);
}

// round 10
// speedup vs baseline: 1.1817x; 1.0808x over previous
#include <cuda_runtime.h>
#include <cstdint>

// ---------------------------------------------------------------------------
// Constants (derived at compile time from reference _compute_offsets()):
//   Level l: scale = 16*2^l - 1, resolution = 16*2^l, verts/axis r1 = 16*2^l+1
//   Dense levels: 0 (r1=17, off 0), 1 (r1=33, off 4920), 2 (r1=65, off 40864)
//   Hashed levels 3..15: 2^19 entries each -> mask; off = 315496+(l-3)*524288
//   TOTAL = 7131240 (even). All level offsets are even.
// ---------------------------------------------------------------------------

#define TOTAL_PARAMS 7131240
#define NPAIRS       (TOTAL_PARAMS / 2)
#define DENSE_TOTAL  315496
#define HASH_MASK    0x7FFFFu
#define PRIME_Y      2654435761u
#define PRIME_Z      805459861u

// Accumulator (85.6 MB). Zero-initialized at load; finalize resets touched
// entries each call (untouched entries are already zero -> skipped).
__device__ __align__(16) float2   g_sum2[TOTAL_PARAMS];   // 57 MB
__device__ __align__(16) unsigned g_cnt[TOTAL_PARAMS];    // 28.5 MB
// Even-pair table: g_pair4[p] = { t[2p], t[2p+1] }. The float2 alias of this
// array IS the flat table t[]. 57 MB (replaces g_table, same footprint).
__device__ __align__(16) float4 g_pair4[NPAIRS];          // 57 MB
// Dense-level x-pair table: g_dense4[i] = { t[i], t[i+1] } for i<DENSE_TOTAL.
__device__ __align__(16) float4 g_dense4[DENSE_TOTAL];    //  5 MB

// ---------------------------------------------------------------------------
// Scatter: 1 point/thread (proven). RED.64 sum + RED.32 count.
// ---------------------------------------------------------------------------
__global__ void __launch_bounds__(256) scatter_kernel(
    const float2* __restrict__ emb, const int* __restrict__ sidx, int n) {
    int i = blockIdx.x * blockDim.x + threadIdx.x;
    if (i >= n) return;
    int idx = sidx[i];
    float2 e = emb[i];
    atomicAdd(&g_sum2[idx], e);
    atomicAdd(&g_cnt[idx], 1u);
}

// ---------------------------------------------------------------------------
// Finalize (+ fused accumulator reset, touched-only):
//   pair4[p] = { v(2p), v(2p+1) },  v(i) = cnt? sum/cnt : fs[i]
// Untouched pairs (57%): sums are already zero -> skip sums read + all resets.
// ---------------------------------------------------------------------------
__global__ void __launch_bounds__(256) finalize_kernel(
    const float4* __restrict__ fs4, int npairs) {
    int p = blockIdx.x * blockDim.x + threadIdx.x;
    if (p >= npairs) return;

    uint2  c  = reinterpret_cast<const uint2*>(g_cnt)[p];
    float4 fv = fs4[p];

    float4 t = fv;
    if ((c.x | c.y) != 0u) {
        float4 s = reinterpret_cast<const float4*>(g_sum2)[p];
        if (c.x > 0u) {
            float inv = 1.0f / (float)c.x;
            t.x = s.x * inv; t.y = s.y * inv;
        }
        if (c.y > 0u) {
            float inv = 1.0f / (float)c.y;
            t.z = s.z * inv; t.w = s.w * inv;
        }
        // Reset touched accumulator pair for the next replay.
        reinterpret_cast<float4*>(g_sum2)[p] = make_float4(0.f, 0.f, 0.f, 0.f);
        reinterpret_cast<uint2*>(g_cnt)[p]   = make_uint2(0u, 0u);
    }
    g_pair4[p] = t;
}

// ---------------------------------------------------------------------------
// Dense pair pack: g_dense4[i] = { t[i], t[i+1] } (reads the L2-hot pair
// table through its flat float2 view).
// ---------------------------------------------------------------------------
__global__ void __launch_bounds__(256) dense_pack_kernel() {
    const float2* t = reinterpret_cast<const float2*>(g_pair4);
    int i = blockIdx.x * blockDim.x + threadIdx.x;
    if (i >= DENSE_TOTAL) return;
    float2 a = t[i];
    float2 b = t[i + 1];            // in-bounds: DENSE_TOTAL < TOTAL_PARAMS
    g_dense4[i] = make_float4(a.x, a.y, b.x, b.y);
}

// ---------------------------------------------------------------------------
// Encode. Dense levels: 4 float4 pair-gathers. Hash levels: when i0 is even
// the two x-neighbor corners land at table indices {j, j^1} (hx0+1 = hx0|1),
// i.e. one aligned even pair -> 4 float4 loads; when i0 is odd, 8 float2
// loads through the flat view (identical to the old path).
// ---------------------------------------------------------------------------
__global__ void __launch_bounds__(256) encode_kernel(
    const float* __restrict__ inp,
    const int*   __restrict__ bound_ptr,
    float*       __restrict__ out,
    int B) {
    int b = blockIdx.x * blockDim.x + threadIdx.x;
    if (b >= B) return;

    float bound = 1.0f;
    if (bound_ptr) {
        int raw = bound_ptr[0];
        bound = (raw > 0 && raw < 1000000) ? (float)raw : __int_as_float(raw);
    }
    const float half_inv = 0.5f / bound;

    float x0 = (inp[3 * b + 0] + bound) * half_inv;
    float x1 = (inp[3 * b + 1] + bound) * half_inv;
    float x2 = (inp[3 * b + 2] + bound) * half_inv;

    const float2* __restrict__ tflat = reinterpret_cast<const float2*>(g_pair4);

    float r[32];

#pragma unroll
    for (int l = 0; l < 16; ++l) {
        const float scale = (float)((16 << l) - 1);
        float p0 = x0 * scale + 0.5f;      // align_corners=False offset
        float p1 = x1 * scale + 0.5f;
        float p2 = x2 * scale + 0.5f;
        float g0 = floorf(p0), g1 = floorf(p1), g2 = floorf(p2);
        float f0 = p0 - g0, f1 = p1 - g1, f2 = p2 - g2;
        int   i0 = (int)g0, i1 = (int)g1, i2 = (int)g2;

        const float wx0 = 1.0f - f0;
        const float wy0 = 1.0f - f1, wy1 = f1;
        const float wz0 = 1.0f - f2, wz1 = f2;
        float ax, ay;

        if (l < 3) {
            // Dense level: x-pair packed float4 gathers (4 loads).
            const int r1  = (l == 0) ? 17 : (l == 1) ? 33 : 65;
            const int off = (l == 0) ? 0  : (l == 1) ? 4920 : 40864;
            const int r1s = r1 * r1;
            int base = off + i0 + i1 * r1 + i2 * r1s;
            float4 d00 = __ldg(&g_dense4[base]);
            float4 d10 = __ldg(&g_dense4[base + r1]);
            float4 d01 = __ldg(&g_dense4[base + r1s]);
            float4 d11 = __ldg(&g_dense4[base + r1 + r1s]);
            float w00 = wy0 * wz0, w10 = wy1 * wz0;
            float w01 = wy0 * wz1, w11 = wy1 * wz1;
            ax = w00 * fmaf(wx0, d00.x, f0 * d00.z)
               + w10 * fmaf(wx0, d10.x, f0 * d10.z)
               + w01 * fmaf(wx0, d01.x, f0 * d01.z)
               + w11 * fmaf(wx0, d11.x, f0 * d11.z);
            ay = w00 * fmaf(wx0, d00.y, f0 * d00.w)
               + w10 * fmaf(wx0, d10.y, f0 * d10.w)
               + w01 * fmaf(wx0, d01.y, f0 * d01.w)
               + w11 * fmaf(wx0, d11.y, f0 * d11.w);
        } else {
            const int off = 315496 + (l - 3) * 524288;   // even
            unsigned hx0 = (unsigned)i0;
            unsigned hy0 = (unsigned)i1 * PRIME_Y;
            unsigned hz0 = (unsigned)i2 * PRIME_Z;
            unsigned hy1 = hy0 + PRIME_Y;
            unsigned hz1 = hz0 + PRIME_Z;
            unsigned t00 = hy0 ^ hz0, t10 = hy1 ^ hz0;
            unsigned t01 = hy0 ^ hz1, t11 = hy1 ^ hz1;

            if ((i0 & 1) == 0) {
                // hx1 = hx0|1 -> corner pair indices are {j, j^1}: one aligned
                // even pair per (y,z) combo -> 4 float4 loads cover 8 corners.
                const int offp = off >> 1;
                unsigned j00 = (hx0 ^ t00) & HASH_MASK;
                unsigned j10 = (hx0 ^ t10) & HASH_MASK;
                unsigned j01 = (hx0 ^ t01) & HASH_MASK;
                unsigned j11 = (hx0 ^ t11) & HASH_MASK;
                float4 q00 = __ldg(&g_pair4[offp + (int)(j00 >> 1)]);
                float4 q10 = __ldg(&g_pair4[offp + (int)(j10 >> 1)]);
                float4 q01 = __ldg(&g_pair4[offp + (int)(j01 >> 1)]);
                float4 q11 = __ldg(&g_pair4[offp + (int)(j11 >> 1)]);
                // If j is odd, the x0-corner sits in .zw and x1-corner in .xy.
                float w00 = wy0 * wz0, w10 = wy1 * wz0;
                float w01 = wy0 * wz1, w11 = wy1 * wz1;
                float lx, hx;
                lx = (j00 & 1) ? q00.z : q00.x;  hx = (j00 & 1) ? q00.x : q00.z;
                ax  = w00 * fmaf(wx0, lx, f0 * hx);
                lx = (j00 & 1) ? q00.w : q00.y;  hx = (j00 & 1) ? q00.y : q00.w;
                ay  = w00 * fmaf(wx0, lx, f0 * hx);
                lx = (j10 & 1) ? q10.z : q10.x;  hx = (j10 & 1) ? q10.x : q10.z;
                ax += w10 * fmaf(wx0, lx, f0 * hx);
                lx = (j10 & 1) ? q10.w : q10.y;  hx = (j10 & 1) ? q10.y : q10.w;
                ay += w10 * fmaf(wx0, lx, f0 * hx);
                lx = (j01 & 1) ? q01.z : q01.x;  hx = (j01 & 1) ? q01.x : q01.z;
                ax += w01 * fmaf(wx0, lx, f0 * hx);
                lx = (j01 & 1) ? q01.w : q01.y;  hx = (j01 & 1) ? q01.y : q01.w;
                ay += w01 * fmaf(wx0, lx, f0 * hx);
                lx = (j11 & 1) ? q11.z : q11.x;  hx = (j11 & 1) ? q11.x : q11.z;
                ax += w11 * fmaf(wx0, lx, f0 * hx);
                lx = (j11 & 1) ? q11.w : q11.y;  hx = (j11 & 1) ? q11.y : q11.w;
                ay += w11 * fmaf(wx0, lx, f0 * hx);
            } else {
                // Odd i0: carry propagates, corners not adjacent -> 8 float2
                // loads through the flat view (same as the old table path).
                unsigned hx1 = hx0 + 1u;
                unsigned idx[8];
#pragma unroll
                for (int c = 0; c < 8; ++c) {
                    unsigned t = ((c >> 1) & 1)
                                   ? (((c >> 2) & 1) ? t11 : t10)
                                   : (((c >> 2) & 1) ? t01 : t00);
                    unsigned h = ((c & 1) ? hx1 : hx0) ^ t;
                    idx[c] = h & HASH_MASK;
                }
                float2 v[8];
#pragma unroll
                for (int c = 0; c < 8; ++c)
                    v[c] = __ldg(&tflat[off + (int)idx[c]]);
                ax = 0.0f; ay = 0.0f;
#pragma unroll
                for (int c = 0; c < 8; ++c) {
                    float w = ((c & 1) ? f0 : wx0) *
                              (((c >> 1) & 1) ? wy1 : wy0) *
                              (((c >> 2) & 1) ? wz1 : wz0);
                    ax = fmaf(w, v[c].x, ax);
                    ay = fmaf(w, v[c].y, ay);
                }
            }
        }
        r[2 * l]     = ax;
        r[2 * l + 1] = ay;
    }

    float4* o = (float4*)(out + (size_t)b * 32);
#pragma unroll
    for (int i = 0; i < 8; ++i)
        o[i] = make_float4(r[4 * i], r[4 * i + 1], r[4 * i + 2], r[4 * i + 3]);
}

// ---------------------------------------------------------------------------
// Launcher: strictly serial, single stream, graph-capturable.
//   scatter -> finalize(pair table + touched-only acc reset) -> dense_pack
//           -> encode
// ---------------------------------------------------------------------------
extern "C" void kernel_launch(void* const* d_in, const int* in_sizes, int n_in,
                              void* d_out, int out_size) {
    const float*  inputs = (const float*) d_in[0];
    const float2* emb    = (const float2*)d_in[1];
    const float4* fs4    = (const float4*)d_in[2];
    const int*    sidx   = (const int*)   d_in[3];
    const int*    bound  = (n_in >= 5) ? (const int*)d_in[4] : nullptr;

    int npts = in_sizes[3];          // 2,000,000
    int B    = in_sizes[0] / 3;      // 262,144

    scatter_kernel<<<(npts + 255) / 256, 256>>>(emb, sidx, npts);
    finalize_kernel<<<(NPAIRS + 255) / 256, 256>>>(fs4, NPAIRS);
    dense_pack_kernel<<<(DENSE_TOTAL + 255) / 256, 256>>>();
    encode_kernel<<<(B + 255) / 256, 256>>>(inputs, bound, (float*)d_out, B);
}